// round 6
// baseline (speedup 1.0000x reference)
#include <cuda_runtime.h>

// Photonic mesh simulator, N=128. R6: warp-per-column layout.
// Each of 128 columns is an independent 509-op chain on 256 complex values.
// One WARP per column: thread t owns pairs 4t..4t+3 (8 complex values in regs).
// - phase + MMI_EVEN: fully register-local (ILP across the 4 pairs)
// - CROSS: 3 of 4 pair-boundaries are thread-local; only the warp boundary
//   needs 4 SHFLs. Zero __syncthreads, zero smem in the mainloop.
// Phase factors exp(i*theta_even) precomputed once to L2-resident scratch,
// loaded as 2x float4 per thread per layer through a 3-deep register queue.

#define N_ 128
#define NLAYERS 255   // 2N-1

// (cos,sin) per (layer, mode); +3 padded layers so the prefetch never goes OOB
__device__ __align__(16) float2 g_cs[(NLAYERS + 3) * N_];

__global__ void precompute_cs_kernel(const float* __restrict__ theta_even) {
    int idx = blockIdx.x * blockDim.x + threadIdx.x;
    if (idx < NLAYERS * N_) {
        float s, c;
        sincosf(theta_even[idx], &s, &c);
        g_cs[idx] = make_float2(c, s);
    } else if (idx < (NLAYERS + 3) * N_) {
        g_cs[idx] = make_float2(1.0f, 0.0f);  // padding (never used in math)
    }
}

__global__ void __launch_bounds__(32, 1) mesh_warp_kernel(
    const float* __restrict__ theta_in,
    const float* __restrict__ theta_out,
    float* __restrict__ out)
{
    // B_mmi = aM*[[p, iq],[iq, p]], aM=sqrt(0.95), p=sqrt(0.505), q=sqrt(0.495)
    constexpr float PM = 0.6926399f;
    constexpr float QM = 0.6857478f;
    // B_x = aX*[[s, it],[it, s]], aX=sqrt(0.98), s=sqrt(0.01), t=sqrt(0.99)
    constexpr float PX = 0.09899495f;
    constexpr float QX = 0.9849873f;
    constexpr float CE = 0.9849873f;   // endpoint scalar aX*sqrt(1-CT)

    const int t   = threadIdx.x;   // 0..31
    const int col = blockIdx.x;    // column
    const int pbase = 4 * t;       // first pair index owned by this thread

    // state: pair i = rows (2(pbase+i), 2(pbase+i)+1) -> (a[i], b[i])
    float2 a[4], b[4];
    #pragma unroll
    for (int i = 0; i < 4; ++i) { a[i] = make_float2(0.f, 0.f); b[i] = make_float2(0.f, 0.f); }

    // init: column col of MMI_IN @ diag(e^{i th_in}) -> pair index col nonzero
    if (col >= pbase && col < pbase + 4) {
        float si, ci;
        sincosf(theta_in[col], &si, &ci);
        int i = col - pbase;
        a[i] = make_float2(PM * ci, PM * si);     // aM*p * e^{i th}
        b[i] = make_float2(-QM * si, QM * ci);    // aM*q * i * e^{i th}
    }

    // phase queue: per layer this thread needs modes 4t..4t+3 => 2 float4
    const float4* cs4 = reinterpret_cast<const float4*>(g_cs) + 2 * t;  // stride 64/layer
    float4 q0a = cs4[0],       q0b = cs4[1];
    float4 q1a = cs4[64],      q1b = cs4[65];
    float4 q2a = cs4[128],     q2b = cs4[129];

    #pragma unroll 2
    for (int k = 0; k < 254; ++k) {
        const float4 qna = cs4[(k + 3) * 64];
        const float4 qnb = cs4[(k + 3) * 64 + 1];

        // unpack (c,s) for the 4 owned modes
        float c[4], s[4];
        c[0] = q0a.x; s[0] = q0a.y; c[1] = q0a.z; s[1] = q0a.w;
        c[2] = q0b.x; s[2] = q0b.y; c[3] = q0b.z; s[3] = q0b.w;

        // Phase(k) on even rows (a), then MMI_EVEN on each pair — ILP x4
        #pragma unroll
        for (int i = 0; i < 4; ++i) {
            float ar = fmaf(a[i].x, c[i], -a[i].y * s[i]);
            float ai = fmaf(a[i].x, s[i],  a[i].y * c[i]);
            float n0r = fmaf(PM, ar,     -QM * b[i].y);
            float n0i = fmaf(PM, ai,      QM * b[i].x);
            float n1r = fmaf(PM, b[i].x, -QM * ai);
            float n1i = fmaf(PM, b[i].y,  QM * ar);
            a[i] = make_float2(n0r, n0i);
            b[i] = make_float2(n1r, n1i);
        }

        // CROSS on even k: pairs (2m+1, 2m+2) == (b[m], a[m+1])
        if ((k & 1) == 0) {
            float pb3x = __shfl_up_sync(0xffffffffu, b[3].x, 1);   // prev thread's b[3]
            float pb3y = __shfl_up_sync(0xffffffffu, b[3].y, 1);
            float na0x = __shfl_down_sync(0xffffffffu, a[0].x, 1); // next thread's a[0]
            float na0y = __shfl_down_sync(0xffffffffu, a[0].y, 1);

            float2 nb0 = make_float2(fmaf(PX, b[0].x, -QX * a[1].y), fmaf(PX, b[0].y, QX * a[1].x));
            float2 na1 = make_float2(fmaf(PX, a[1].x, -QX * b[0].y), fmaf(PX, a[1].y, QX * b[0].x));
            float2 nb1 = make_float2(fmaf(PX, b[1].x, -QX * a[2].y), fmaf(PX, b[1].y, QX * a[2].x));
            float2 na2 = make_float2(fmaf(PX, a[2].x, -QX * b[1].y), fmaf(PX, a[2].y, QX * b[1].x));
            float2 nb2 = make_float2(fmaf(PX, b[2].x, -QX * a[3].y), fmaf(PX, b[2].y, QX * a[3].x));
            float2 na3 = make_float2(fmaf(PX, a[3].x, -QX * b[2].y), fmaf(PX, a[3].y, QX * b[2].x));

            float2 na0, nb3;
            if (t > 0) {
                na0 = make_float2(fmaf(PX, a[0].x, -QX * pb3y), fmaf(PX, a[0].y, QX * pb3x));
            } else {            // global row 0 endpoint
                na0 = make_float2(CE * a[0].x, CE * a[0].y);
            }
            if (t < 31) {
                nb3 = make_float2(fmaf(PX, b[3].x, -QX * na0y), fmaf(PX, b[3].y, QX * na0x));
            } else {            // global row 2N-1 endpoint
                nb3 = make_float2(CE * b[3].x, CE * b[3].y);
            }
            a[0] = na0; a[1] = na1; a[2] = na2; a[3] = na3;
            b[0] = nb0; b[1] = nb1; b[2] = nb2; b[3] = nb3;
        }

        q0a = q1a; q0b = q1b;
        q1a = q2a; q1b = q2b;
        q2a = qna; q2b = qnb;
    }

    // Phase(254): phase only, on even rows
    {
        float c[4], s[4];
        c[0] = q0a.x; s[0] = q0a.y; c[1] = q0a.z; s[1] = q0a.w;
        c[2] = q0b.x; s[2] = q0b.y; c[3] = q0b.z; s[3] = q0b.w;
        #pragma unroll
        for (int i = 0; i < 4; ++i) {
            float ar = fmaf(a[i].x, c[i], -a[i].y * s[i]);
            float ai = fmaf(a[i].x, s[i],  a[i].y * c[i]);
            a[i] = make_float2(ar, ai);
        }
    }

    // MMI_OUT + output phase; float32 output = real part, row-major [m][col]
    #pragma unroll
    for (int i = 0; i < 4; ++i) {
        const int m = pbase + i;
        float orr = fmaf(PM, a[i].x, -QM * b[i].y);
        float oii = fmaf(PM, a[i].y,  QM * b[i].x);
        float so, co;
        sincosf(theta_out[m], &so, &co);
        out[m * N_ + col] = fmaf(orr, co, -oii * so);
    }
}

extern "C" void kernel_launch(void* const* d_in, const int* in_sizes, int n_in,
                              void* d_out, int out_size) {
    // theta_even is the (2N-1)*N array; theta_in first N-sized, theta_out second.
    const float* theta_even = nullptr;
    const float* smalls[2] = {nullptr, nullptr};
    int ns = 0;
    for (int i = 0; i < n_in; ++i) {
        if (in_sizes[i] == NLAYERS * N_) {
            theta_even = (const float*)d_in[i];
        } else if (ns < 2) {
            smalls[ns++] = (const float*)d_in[i];
        }
    }
    const float* theta_in  = smalls[0];
    const float* theta_out = smalls[1];

    precompute_cs_kernel<<<(NLAYERS + 3), N_>>>(theta_even);
    mesh_warp_kernel<<<N_, 32>>>(theta_in, theta_out, (float*)d_out);
}

// round 7
// speedup vs baseline: 1.3775x; 1.3775x over previous
#include <cuda_runtime.h>

// Photonic mesh simulator, N=128. R7: warp-per-column + copy-free 4-deep
// phase-factor ring (fixes R6's 1-layer effective prefetch distance).
// One WARP per column: thread t owns pairs 4t..4t+3 (8 complex values in regs).
// Mainloop: 63 x (4 fully-unrolled layers); layer k consumes ring slot k&3 and
// reloads it with layer k+4 (load->use = 4 layers ~ 300+ cyc > L2 234 cyc).
// Zero __syncthreads, zero smem; cross uses 4 SHFLs at the warp-internal
// boundaries only.

#define N_ 128
#define NLAYERS 255   // 2N-1

// (cos,sin) per (layer, mode); +5 padded layers so the ring prefetch never OOBs
__device__ __align__(16) float2 g_cs[(NLAYERS + 5) * N_];

__global__ void precompute_cs_kernel(const float* __restrict__ theta_even) {
    int idx = blockIdx.x * blockDim.x + threadIdx.x;
    if (idx < NLAYERS * N_) {
        float s, c;
        sincosf(theta_even[idx], &s, &c);
        g_cs[idx] = make_float2(c, s);
    } else if (idx < (NLAYERS + 5) * N_) {
        g_cs[idx] = make_float2(1.0f, 0.0f);  // padding (never used in math)
    }
}

__global__ void __launch_bounds__(32, 1) mesh_warp_kernel(
    const float* __restrict__ theta_in,
    const float* __restrict__ theta_out,
    float* __restrict__ out)
{
    // B_mmi = aM*[[p, iq],[iq, p]], aM=sqrt(0.95), p=sqrt(0.505), q=sqrt(0.495)
    constexpr float PM = 0.6926399f;
    constexpr float QM = 0.6857478f;
    // B_x = aX*[[s, it],[it, s]], aX=sqrt(0.98), s=sqrt(0.01), t=sqrt(0.99)
    constexpr float PX = 0.09899495f;
    constexpr float QX = 0.9849873f;
    constexpr float CE = 0.9849873f;   // endpoint scalar aX*sqrt(1-CT)

    const int t   = threadIdx.x;   // 0..31
    const int col = blockIdx.x;    // column
    const int pbase = 4 * t;       // first pair index owned by this thread

    // state: pair i = rows (2(pbase+i), 2(pbase+i)+1) -> (a[i], b[i])
    float2 a[4], b[4];
    #pragma unroll
    for (int i = 0; i < 4; ++i) { a[i] = make_float2(0.f, 0.f); b[i] = make_float2(0.f, 0.f); }

    // init: column col of MMI_IN @ diag(e^{i th_in}) -> pair index col nonzero
    if (col >= pbase && col < pbase + 4) {
        float si, ci;
        sincosf(theta_in[col], &si, &ci);
        int i = col - pbase;
        a[i] = make_float2(PM * ci, PM * si);     // aM*p * e^{i th}
        b[i] = make_float2(-QM * si, QM * ci);    // aM*q * i * e^{i th}
    }

    // phase ring: per layer this thread needs modes 4t..4t+3 => 2 float4.
    // 4-deep ring, slot j holds layer (k: k&3==j). 64 float4 per layer stride.
    const float4* cs4 = reinterpret_cast<const float4*>(g_cs) + 2 * t;
    float4 qa[4], qb[4];
    #pragma unroll
    for (int j = 0; j < 4; ++j) {
        qa[j] = cs4[j * 64];
        qb[j] = cs4[j * 64 + 1];
    }

    // one MMI layer (phase on even rows, then 2x2 mix); cross is compile-time
    auto do_layer = [&](float4 la, float4 lb, bool docross) {
        float c[4], s[4];
        c[0] = la.x; s[0] = la.y; c[1] = la.z; s[1] = la.w;
        c[2] = lb.x; s[2] = lb.y; c[3] = lb.z; s[3] = lb.w;
        #pragma unroll
        for (int i = 0; i < 4; ++i) {
            float ar = fmaf(a[i].x, c[i], -a[i].y * s[i]);
            float ai = fmaf(a[i].x, s[i],  a[i].y * c[i]);
            float n0r = fmaf(PM, ar,     -QM * b[i].y);
            float n0i = fmaf(PM, ai,      QM * b[i].x);
            float n1r = fmaf(PM, b[i].x, -QM * ai);
            float n1i = fmaf(PM, b[i].y,  QM * ar);
            a[i] = make_float2(n0r, n0i);
            b[i] = make_float2(n1r, n1i);
        }
        if (docross) {
            float pb3x = __shfl_up_sync(0xffffffffu, b[3].x, 1);   // prev thread's b[3]
            float pb3y = __shfl_up_sync(0xffffffffu, b[3].y, 1);
            float na0x = __shfl_down_sync(0xffffffffu, a[0].x, 1); // next thread's a[0]
            float na0y = __shfl_down_sync(0xffffffffu, a[0].y, 1);

            float2 nb0 = make_float2(fmaf(PX, b[0].x, -QX * a[1].y), fmaf(PX, b[0].y, QX * a[1].x));
            float2 na1 = make_float2(fmaf(PX, a[1].x, -QX * b[0].y), fmaf(PX, a[1].y, QX * b[0].x));
            float2 nb1 = make_float2(fmaf(PX, b[1].x, -QX * a[2].y), fmaf(PX, b[1].y, QX * a[2].x));
            float2 na2 = make_float2(fmaf(PX, a[2].x, -QX * b[1].y), fmaf(PX, a[2].y, QX * b[1].x));
            float2 nb2 = make_float2(fmaf(PX, b[2].x, -QX * a[3].y), fmaf(PX, b[2].y, QX * a[3].x));
            float2 na3 = make_float2(fmaf(PX, a[3].x, -QX * b[2].y), fmaf(PX, a[3].y, QX * b[2].x));

            float2 na0, nb3;
            if (t > 0) {
                na0 = make_float2(fmaf(PX, a[0].x, -QX * pb3y), fmaf(PX, a[0].y, QX * pb3x));
            } else {            // global row 0 endpoint
                na0 = make_float2(CE * a[0].x, CE * a[0].y);
            }
            if (t < 31) {
                nb3 = make_float2(fmaf(PX, b[3].x, -QX * na0y), fmaf(PX, b[3].y, QX * na0x));
            } else {            // global row 2N-1 endpoint
                nb3 = make_float2(CE * b[3].x, CE * b[3].y);
            }
            a[0] = na0; a[1] = na1; a[2] = na2; a[3] = na3;
            b[0] = nb0; b[1] = nb1; b[2] = nb2; b[3] = nb3;
        }
    };

    // mainloop: layers 0..251 in 63 groups of 4; slot j <=> layer parity j&1
    const float4* pre = cs4 + 4 * 64;   // points at layer k+4 for k=0
    for (int kk = 0; kk < 63; ++kk) {
        #pragma unroll
        for (int j = 0; j < 4; ++j) {
            float4 la = qa[j], lb = qb[j];
            qa[j] = pre[j * 64];          // prefetch layer k+4 into freed slot
            qb[j] = pre[j * 64 + 1];
            do_layer(la, lb, (j & 1) == 0);   // k even <=> j even
        }
        pre += 4 * 64;
    }
    // epilogue: layer 252 (cross) and 253 (no cross), already resident
    do_layer(qa[0], qb[0], true);
    do_layer(qa[1], qb[1], false);

    // Phase(254): phase only, factors resident in slot 2
    {
        float c[4], s[4];
        c[0] = qa[2].x; s[0] = qa[2].y; c[1] = qa[2].z; s[1] = qa[2].w;
        c[2] = qb[2].x; s[2] = qb[2].y; c[3] = qb[2].z; s[3] = qb[2].w;
        #pragma unroll
        for (int i = 0; i < 4; ++i) {
            float ar = fmaf(a[i].x, c[i], -a[i].y * s[i]);
            float ai = fmaf(a[i].x, s[i],  a[i].y * c[i]);
            a[i] = make_float2(ar, ai);
        }
    }

    // MMI_OUT + output phase; float32 output = real part, row-major [m][col]
    #pragma unroll
    for (int i = 0; i < 4; ++i) {
        const int m = pbase + i;
        float orr = fmaf(PM, a[i].x, -QM * b[i].y);
        float oii = fmaf(PM, a[i].y,  QM * b[i].x);
        float so, co;
        sincosf(theta_out[m], &so, &co);
        out[m * N_ + col] = fmaf(orr, co, -oii * so);
    }
}

extern "C" void kernel_launch(void* const* d_in, const int* in_sizes, int n_in,
                              void* d_out, int out_size) {
    // theta_even is the (2N-1)*N array; theta_in first N-sized, theta_out second.
    const float* theta_even = nullptr;
    const float* smalls[2] = {nullptr, nullptr};
    int ns = 0;
    for (int i = 0; i < n_in; ++i) {
        if (in_sizes[i] == NLAYERS * N_) {
            theta_even = (const float*)d_in[i];
        } else if (ns < 2) {
            smalls[ns++] = (const float*)d_in[i];
        }
    }
    const float* theta_in  = smalls[0];
    const float* theta_out = smalls[1];

    precompute_cs_kernel<<<(NLAYERS + 5), N_>>>(theta_even);
    mesh_warp_kernel<<<N_, 32>>>(theta_in, theta_out, (float*)d_out);
}